// round 16
// baseline (speedup 1.0000x reference)
#include <cuda_runtime.h>
#include <cuda_fp16.h>
#include <cstdint>
#include <cstddef>

// ---------------------------------------------------------------------------
// GCN, fp16-native dataflow.
//   prep (1 kernel): deg=0, status=0, xh=fp16(x), Wt=fp16(W^T)
//   CSR build: count (rank persisted) -> scanall (single-wave) ->
//              place (atomic-free: off[dst]+rank)
//   per layer: h = fp16(dinv .* (relu(A)@W))  [HMMA, cp.async]
//              a = fp16(dinv .* csr_sum(h) + b)  (final layer -> fp32 out)
//   agg: ISSUE-bound -> 16 lanes/node x uint4 loads (half the LDG + csr
//   loads) + depth-3 fp16 __hadd2 tree (1 convert + 1 fp32-add per 8 edges).
// ---------------------------------------------------------------------------

#define MAX_NODES 100000
#define PAD_ROWS  100096           // 782 tiles * 128
#define MAX_EDGES 1600000
#define SCAN_BLK  1024
#define NB_MAX    128
#define APITCH    136              // halves per smem row
#define AGG_FLAG  0x40000000

__device__ __half g_h [(size_t)PAD_ROWS * 128];   // GEMM output / gather src
__device__ __half g_a [(size_t)PAD_ROWS * 128];   // agg output / GEMM input
__device__ __half g_wt[3 * 128 * 128];            // fp16 W^T: [n][k]
__device__ int    g_deg [MAX_NODES];
__device__ float  g_dinv[MAX_NODES];
__device__ int    g_off [MAX_NODES + 1];
__device__ int    g_rank[MAX_EDGES];
__device__ int    g_csr [MAX_EDGES];
__device__ int    g_status[NB_MAX];

#define H2(u) (*(const __half2*)&(u))

// ================= fused prep: zero deg/status + cvt x + build Wt ==========
__global__ void __launch_bounds__(256)
k_prep(const float* __restrict__ x, __half* __restrict__ xh,
       int* __restrict__ deg, int* __restrict__ status,
       const float* __restrict__ W1, const float* __restrict__ W2,
       const float* __restrict__ W3, __half* __restrict__ wt,
       int n4, int M, int nbCvt, int nbZero) {
    int b = blockIdx.x;
    if (b < nbCvt) {
        int i = b * 256 + threadIdx.x;
        if (i < n4) {
            float4 v = __ldg((const float4*)x + i);
            __half2* p = (__half2*)(xh + (size_t)i * 4);
            p[0] = __floats2half2_rn(v.x, v.y);
            p[1] = __floats2half2_rn(v.z, v.w);
        }
    } else if (b < nbCvt + nbZero) {
        int i = (b - nbCvt) * 256 + threadIdx.x;
        if (i < M) deg[i] = 0;
        if (i < NB_MAX) status[i] = 0;
    } else {
        int i = (b - nbCvt - nbZero) * 256 + threadIdx.x;
        if (i < 16384) {
            int k = i >> 7, n = i & 127;
            wt[n * 128 + k] = __float2half_rn(__ldg(W1 + k * 128 + n));
        } else if (i < 32768) {
            int j = i - 16384, k = j >> 7, n = j & 127;
            wt[16384 + n * 128 + k] = __float2half_rn(__ldg(W2 + k * 128 + n));
        } else if (i < 40960) {
            int j = i - 32768, k = j >> 6, n = j & 63;
            wt[32768 + n * 128 + k] = __float2half_rn(__ldg(W3 + k * 64 + n));
        }
    }
}

// ======================= CSR build =========================================
__global__ void k_count(int* deg, const int* __restrict__ dst,
                        int* __restrict__ rank, int E) {
    int e = blockIdx.x * blockDim.x + threadIdx.x;
    if (e < E) rank[e] = atomicAdd(&deg[dst[e]], 1);
}

__global__ void __launch_bounds__(SCAN_BLK)
k_scanall(const int* __restrict__ deg, int* __restrict__ off,
          float* __restrict__ dinv, int* status, int n, int E) {
    __shared__ int sh[SCAN_BLK];
    __shared__ int s_excl;
    const int tid  = threadIdx.x;
    const int tile = blockIdx.x;
    const int i = tile * SCAN_BLK + tid;

    int x = (i < n) ? deg[i] : 0;
    if (i < n) dinv[i] = (x > 0) ? rsqrtf((float)x) : 0.0f;
    sh[tid] = x;
    __syncthreads();
#pragma unroll
    for (int s = 1; s < SCAN_BLK; s <<= 1) {
        int v = (tid >= s) ? sh[tid - s] : 0;
        __syncthreads();
        sh[tid] += v;
        __syncthreads();
    }
    int incl = sh[tid];

    if (tid == SCAN_BLK - 1)
        atomicExch(&status[tile], sh[SCAN_BLK - 1] | AGG_FLAG);

    if (tid < 32) {
        int sum = 0;
        for (int t = tid; t < tile; t += 32) {
            int s;
            do { s = atomicAdd(&status[t], 0); } while (!(s & AGG_FLAG));
            sum += s & 0x3FFFFFFF;
        }
#pragma unroll
        for (int o = 16; o; o >>= 1) sum += __shfl_xor_sync(0xFFFFFFFF, sum, o);
        if (tid == 0) s_excl = sum;
    }
    __syncthreads();

    if (i < n) off[i] = s_excl + incl - x;   // exclusive
    if (i == 0) off[n] = E;
}

__global__ void k_place(const int* __restrict__ src, const int* __restrict__ dst,
                        const int* __restrict__ off, const int* __restrict__ rank,
                        int* __restrict__ csr, int E) {
    int e = blockIdx.x * blockDim.x + threadIdx.x;
    if (e < E) {
        int slot = __ldg(off + dst[e]) + rank[e];
        csr[slot] = src[e];
    }
}

// ======================= HMMA GEMM (fp16 in/out, cp.async) =================
__device__ __forceinline__ void ldmx4(uint32_t* r, uint32_t addr) {
    asm volatile("ldmatrix.sync.aligned.m8n8.x4.shared.b16 {%0,%1,%2,%3}, [%4];"
                 : "=r"(r[0]), "=r"(r[1]), "=r"(r[2]), "=r"(r[3]) : "r"(addr));
}
__device__ __forceinline__ void ldmx2(uint32_t* r, uint32_t addr) {
    asm volatile("ldmatrix.sync.aligned.m8n8.x2.shared.b16 {%0,%1}, [%2];"
                 : "=r"(r[0]), "=r"(r[1]) : "r"(addr));
}
__device__ __forceinline__ void mma16816(float* c, const uint32_t* a, const uint32_t* b) {
    asm volatile("mma.sync.aligned.m16n8k16.row.col.f32.f16.f16.f32 "
                 "{%0,%1,%2,%3}, {%4,%5,%6,%7}, {%8,%9}, {%0,%1,%2,%3};"
                 : "+f"(c[0]), "+f"(c[1]), "+f"(c[2]), "+f"(c[3])
                 : "r"(a[0]), "r"(a[1]), "r"(a[2]), "r"(a[3]), "r"(b[0]), "r"(b[1]));
}
__device__ __forceinline__ void cpa16(uint32_t smem, const void* gmem) {
    asm volatile("cp.async.cg.shared.global [%0], [%1], 16;" :: "r"(smem), "l"(gmem));
}

template <int BN>
__global__ void __launch_bounds__(BN * 2)
k_gemm(const __half* __restrict__ A, const __half* __restrict__ Wt,
       __half* __restrict__ C, const float* __restrict__ dinv,
       int M, int relu_in) {
    constexpr int NT  = BN * 2;
    constexpr int NWN = BN / 32;

    extern __shared__ __half sm[];
    __half* As  = sm;                    // [128][APITCH]
    __half* Wts = sm + 128 * APITCH;     // [BN][APITCH]

    const int tid  = threadIdx.x;
    const int wid  = tid >> 5;
    const int lane = tid & 31;
    const int wm   = wid / NWN;
    const int wn   = wid % NWN;
    const int brow = blockIdx.x * 128;

    const uint32_t asb = (uint32_t)__cvta_generic_to_shared(As);
    const uint32_t wsb = (uint32_t)__cvta_generic_to_shared(Wts);

#pragma unroll
    for (int idx = tid; idx < 128 * 16; idx += NT) {
        int row = idx >> 4, ch = idx & 15;
        cpa16(asb + (uint32_t)(row * APITCH + ch * 8) * 2,
              A + ((size_t)(brow + row) * 128 + ch * 8));
    }
#pragma unroll
    for (int idx = tid; idx < BN * 16; idx += NT) {
        int n = idx >> 4, ch = idx & 15;
        cpa16(wsb + (uint32_t)(n * APITCH + ch * 8) * 2,
              Wt + ((size_t)n * 128 + ch * 8));
    }
    asm volatile("cp.async.commit_group;");
    asm volatile("cp.async.wait_group 0;" ::: "memory");
    __syncthreads();

    float acc[4][4][4];
#pragma unroll
    for (int i = 0; i < 4; i++)
#pragma unroll
        for (int j = 0; j < 4; j++)
#pragma unroll
            for (int q = 0; q < 4; q++) acc[i][j][q] = 0.0f;

    const int aRow0 = wm * 64 + (lane & 15);
    const int aKoff = (lane >> 4) * 8;
    const int bRow0 = wn * 32 + (lane & 7);
    const int bKoff = ((lane >> 3) & 1) * 8;
    const __half2 z2 = __floats2half2_rn(0.f, 0.f);

#pragma unroll
    for (int ks = 0; ks < 8; ks++) {
        uint32_t a[4][4], b[4][2];
#pragma unroll
        for (int mf = 0; mf < 4; mf++)
            ldmx4(a[mf], asb + (uint32_t)(((aRow0 + mf * 16) * APITCH) + ks * 16 + aKoff) * 2);
        if (relu_in) {
#pragma unroll
            for (int mf = 0; mf < 4; mf++)
#pragma unroll
                for (int q = 0; q < 4; q++) {
                    __half2 v = *(__half2*)&a[mf][q];
                    v = __hmax2(v, z2);
                    a[mf][q] = *(uint32_t*)&v;
                }
        }
#pragma unroll
        for (int nf = 0; nf < 4; nf++)
            ldmx2(b[nf], wsb + (uint32_t)(((bRow0 + nf * 8) * APITCH) + ks * 16 + bKoff) * 2);
#pragma unroll
        for (int mf = 0; mf < 4; mf++)
#pragma unroll
            for (int nf = 0; nf < 4; nf++)
                mma16816(acc[mf][nf], a[mf], b[nf]);
    }

    // ---- epilogue: dinv scale, fp16 store ----
    const int rbase = brow + wm * 64 + (lane >> 2);
    const int cbase = wn * 32 + (lane & 3) * 2;
#pragma unroll
    for (int mf = 0; mf < 4; mf++) {
        int r0 = rbase + mf * 16;
        int r1 = r0 + 8;
        float s0 = (r0 < M) ? __ldg(dinv + r0) : 0.0f;
        float s1 = (r1 < M) ? __ldg(dinv + r1) : 0.0f;
#pragma unroll
        for (int nf = 0; nf < 4; nf++) {
            int col = cbase + nf * 8;
            if (r0 < M)
                *(__half2*)(C + (size_t)r0 * BN + col) =
                    __floats2half2_rn(acc[mf][nf][0] * s0, acc[mf][nf][1] * s0);
            if (r1 < M)
                *(__half2*)(C + (size_t)r1 * BN + col) =
                    __floats2half2_rn(acc[mf][nf][2] * s1, acc[mf][nf][3] * s1);
        }
    }
}

// ===================== CSR gather-sum ======================================
// 16 lanes/node, uint4 (16B) loads, depth-3 fp16 tree (8 edges/convert).
__global__ void __launch_bounds__(256)
k_agg128(const __half* __restrict__ h, const int* __restrict__ off,
         const int* __restrict__ csr, const float* __restrict__ dinv,
         const float* __restrict__ bias, __half* __restrict__ out, int Nn) {
    int gt = blockIdx.x * blockDim.x + threadIdx.x;
    int node = gt >> 4;
    int lane = gt & 15;
    if (node >= Nn) return;
    int i  = __ldg(off + node);
    int s1 = __ldg(off + node + 1);
    const uint4* hp = (const uint4*)h;   // row stride = 16 uint4

    float2 acc[4];
#pragma unroll
    for (int q = 0; q < 4; q++) acc[q] = make_float2(0.f, 0.f);

#pragma unroll 1
    for (; i + 8 <= s1; i += 8) {
        int s[8];
#pragma unroll
        for (int j = 0; j < 8; j++) s[j] = __ldg(csr + i + j);
        uint4 v[8];
#pragma unroll
        for (int j = 0; j < 8; j++) v[j] = __ldg(hp + (size_t)s[j] * 16 + lane);
        // depth-3 fp16 tree per word, one convert per 8 edges
#pragma unroll
        for (int q = 0; q < 4; q++) {
            const uint32_t* w0 = &v[0].x;
            __half2 t01 = __hadd2(H2((&v[0].x)[q]), H2((&v[1].x)[q]));
            __half2 t23 = __hadd2(H2((&v[2].x)[q]), H2((&v[3].x)[q]));
            __half2 t45 = __hadd2(H2((&v[4].x)[q]), H2((&v[5].x)[q]));
            __half2 t67 = __hadd2(H2((&v[6].x)[q]), H2((&v[7].x)[q]));
            __half2 t = __hadd2(__hadd2(t01, t23), __hadd2(t45, t67));
            float2 f = __half22float2(t);
            acc[q].x += f.x; acc[q].y += f.y;
            (void)w0;
        }
    }
    for (; i < s1; i++) {
        int s = __ldg(csr + i);
        uint4 v = __ldg(hp + (size_t)s * 16 + lane);
#pragma unroll
        for (int q = 0; q < 4; q++) {
            float2 f = __half22float2(H2((&v.x)[q]));
            acc[q].x += f.x; acc[q].y += f.y;
        }
    }
    float dv = __ldg(dinv + node);
    float4 bv0 = __ldg((const float4*)bias + lane * 2);
    float4 bv1 = __ldg((const float4*)bias + lane * 2 + 1);
    __half2 o0 = __floats2half2_rn(acc[0].x * dv + bv0.x, acc[0].y * dv + bv0.y);
    __half2 o1 = __floats2half2_rn(acc[1].x * dv + bv0.z, acc[1].y * dv + bv0.w);
    __half2 o2 = __floats2half2_rn(acc[2].x * dv + bv1.x, acc[2].y * dv + bv1.y);
    __half2 o3 = __floats2half2_rn(acc[3].x * dv + bv1.z, acc[3].y * dv + bv1.w);
    uint4 ov;
    ov.x = *(uint32_t*)&o0; ov.y = *(uint32_t*)&o1;
    ov.z = *(uint32_t*)&o2; ov.w = *(uint32_t*)&o3;
    *((uint4*)out + (size_t)node * 16 + lane) = ov;
}

// C=64 (final, fp32 out): 8 lanes/node, uint4 loads, depth-3 tree.
__global__ void __launch_bounds__(256)
k_agg64(const __half* __restrict__ h, const int* __restrict__ off,
        const int* __restrict__ csr, const float* __restrict__ dinv,
        const float* __restrict__ bias, float* __restrict__ out, int Nn) {
    int gt = blockIdx.x * blockDim.x + threadIdx.x;
    int node = gt >> 3;
    int lane = gt & 7;
    if (node >= Nn) return;
    int i  = __ldg(off + node);
    int s1 = __ldg(off + node + 1);
    const uint4* hp = (const uint4*)h;   // row stride = 8 uint4

    float2 acc[4];
#pragma unroll
    for (int q = 0; q < 4; q++) acc[q] = make_float2(0.f, 0.f);

#pragma unroll 1
    for (; i + 8 <= s1; i += 8) {
        int s[8];
#pragma unroll
        for (int j = 0; j < 8; j++) s[j] = __ldg(csr + i + j);
        uint4 v[8];
#pragma unroll
        for (int j = 0; j < 8; j++) v[j] = __ldg(hp + (size_t)s[j] * 8 + lane);
#pragma unroll
        for (int q = 0; q < 4; q++) {
            __half2 t01 = __hadd2(H2((&v[0].x)[q]), H2((&v[1].x)[q]));
            __half2 t23 = __hadd2(H2((&v[2].x)[q]), H2((&v[3].x)[q]));
            __half2 t45 = __hadd2(H2((&v[4].x)[q]), H2((&v[5].x)[q]));
            __half2 t67 = __hadd2(H2((&v[6].x)[q]), H2((&v[7].x)[q]));
            __half2 t = __hadd2(__hadd2(t01, t23), __hadd2(t45, t67));
            float2 f = __half22float2(t);
            acc[q].x += f.x; acc[q].y += f.y;
        }
    }
    for (; i < s1; i++) {
        int s = __ldg(csr + i);
        uint4 v = __ldg(hp + (size_t)s * 8 + lane);
#pragma unroll
        for (int q = 0; q < 4; q++) {
            float2 f = __half22float2(H2((&v.x)[q]));
            acc[q].x += f.x; acc[q].y += f.y;
        }
    }
    float dv = __ldg(dinv + node);
    float4 bv0 = __ldg((const float4*)bias + lane * 2);
    float4 bv1 = __ldg((const float4*)bias + lane * 2 + 1);
    float* op = out + (size_t)node * 64 + lane * 8;
    float4 o0 = make_float4(acc[0].x * dv + bv0.x, acc[0].y * dv + bv0.y,
                            acc[1].x * dv + bv0.z, acc[1].y * dv + bv0.w);
    float4 o1 = make_float4(acc[2].x * dv + bv1.x, acc[2].y * dv + bv1.y,
                            acc[3].x * dv + bv1.z, acc[3].y * dv + bv1.w);
    *(float4*)op       = o0;
    *(float4*)(op + 4) = o1;
}

// ---------------------------------------------------------------------------
extern "C" void kernel_launch(void* const* d_in, const int* in_sizes, int n_in,
                              void* d_out, int out_size) {
    const float* x  = (const float*)d_in[0];
    const int*   ei = (const int*)  d_in[1];
    const float* W1 = (const float*)d_in[2];
    const float* b1 = (const float*)d_in[3];
    const float* W2 = (const float*)d_in[4];
    const float* b2 = (const float*)d_in[5];
    const float* W3 = (const float*)d_in[6];
    const float* b3 = (const float*)d_in[7];

    const int E = in_sizes[1] / 2;
    const int M = in_sizes[0] / 128;
    const int* src = ei;
    const int* dst = ei + E;

    __half *h, *a, *wt;
    float* dinv;
    int *deg, *off, *rank, *csr, *status;
    cudaGetSymbolAddress((void**)&h,      g_h);
    cudaGetSymbolAddress((void**)&a,      g_a);
    cudaGetSymbolAddress((void**)&wt,     g_wt);
    cudaGetSymbolAddress((void**)&deg,    g_deg);
    cudaGetSymbolAddress((void**)&dinv,   g_dinv);
    cudaGetSymbolAddress((void**)&off,    g_off);
    cudaGetSymbolAddress((void**)&rank,   g_rank);
    cudaGetSymbolAddress((void**)&csr,    g_csr);
    cudaGetSymbolAddress((void**)&status, g_status);
    float* out = (float*)d_out;

    const int nb = (M + SCAN_BLK - 1) / SCAN_BLK;
    const int smem128 = (128 + 128) * APITCH * 2;   // 69632
    const int smem64  = (128 + 64)  * APITCH * 2;   // 52224
    cudaFuncSetAttribute(k_gemm<128>, cudaFuncAttributeMaxDynamicSharedMemorySize, smem128);
    cudaFuncSetAttribute(k_gemm<64>,  cudaFuncAttributeMaxDynamicSharedMemorySize, smem64);

    // --- fused prep: deg=0, status=0, xh=fp16(x), Wt=fp16(W^T) ---
    const int n4     = M * 32;
    const int nbCvt  = (n4 + 255) / 256;
    const int nbZero = (M + 255) / 256;
    const int nbWt   = (40960 + 255) / 256;
    k_prep<<<nbCvt + nbZero + nbWt, 256>>>(x, a, deg, status, W1, W2, W3, wt,
                                           n4, M, nbCvt, nbZero);

    // --- CSR build (rank captured in count; place is atomic-free) ---
    k_count  <<<(E + 255) / 256, 256>>>(deg, dst, rank, E);
    k_scanall<<<nb, SCAN_BLK>>>(deg, off, dinv, status, M, E);
    k_place  <<<(E + 255) / 256, 256>>>(src, dst, off, rank, csr, E);

    const int gtiles = (M + 127) / 128;

    // --- layer 1 ---
    k_gemm<128><<<gtiles, 256, smem128>>>(a, wt, h, dinv, M, 0);
    k_agg128<<<(M * 16 + 255) / 256, 256>>>(h, off, csr, dinv, b1, a, M);

    // --- layer 2 ---
    k_gemm<128><<<gtiles, 256, smem128>>>(a, wt + 16384, h, dinv, M, 1);
    k_agg128<<<(M * 16 + 255) / 256, 256>>>(h, off, csr, dinv, b2, a, M);

    // --- layer 3 (N=64) ---
    k_gemm<64><<<gtiles, 128, smem64>>>(a, wt + 32768, h, dinv, M, 1);
    k_agg64<<<(M * 8 + 255) / 256, 256>>>(h, off, csr, dinv, b3, out, M);
}

// round 17
// speedup vs baseline: 1.0597x; 1.0597x over previous
#include <cuda_runtime.h>
#include <cuda_fp16.h>
#include <cstdint>
#include <cstddef>

// ---------------------------------------------------------------------------
// GCN, fp16-native dataflow.  (R15 winner layout restored: 32 lanes/node,
// 8B loads -- R16's 16-lane variant halved gather MLP and regressed.)
//   prep (1 kernel): deg=0, status=0, xh=fp16(x), Wt=fp16(W^T)
//   CSR build: count (rank persisted) -> scanall (single-wave) ->
//              place (atomic-free: off[dst]+rank)
//   per layer: h = fp16(dinv .* (relu(A)@W))  [HMMA, cp.async]
//              a = fp16(dinv .* csr_sum(h) + b)  (final layer -> fp32 out)
//   agg: warp=node, depth-3 fp16 __hadd2 tree over 8-edge groups
//   (1 convert + 1 fp32 add per word per 8 edges).
// ---------------------------------------------------------------------------

#define MAX_NODES 100000
#define PAD_ROWS  100096           // 782 tiles * 128
#define MAX_EDGES 1600000
#define SCAN_BLK  1024
#define NB_MAX    128
#define APITCH    136              // halves per smem row
#define AGG_FLAG  0x40000000

__device__ __half g_h [(size_t)PAD_ROWS * 128];   // GEMM output / gather src
__device__ __half g_a [(size_t)PAD_ROWS * 128];   // agg output / GEMM input
__device__ __half g_wt[3 * 128 * 128];            // fp16 W^T: [n][k]
__device__ int    g_deg [MAX_NODES];
__device__ float  g_dinv[MAX_NODES];
__device__ int    g_off [MAX_NODES + 1];
__device__ int    g_rank[MAX_EDGES];
__device__ int    g_csr [MAX_EDGES];
__device__ int    g_status[NB_MAX];

#define H2(u) (*(const __half2*)&(u))

// ================= fused prep: zero deg/status + cvt x + build Wt ==========
__global__ void __launch_bounds__(256)
k_prep(const float* __restrict__ x, __half* __restrict__ xh,
       int* __restrict__ deg, int* __restrict__ status,
       const float* __restrict__ W1, const float* __restrict__ W2,
       const float* __restrict__ W3, __half* __restrict__ wt,
       int n4, int M, int nbCvt, int nbZero) {
    int b = blockIdx.x;
    if (b < nbCvt) {
        int i = b * 256 + threadIdx.x;
        if (i < n4) {
            float4 v = __ldg((const float4*)x + i);
            __half2* p = (__half2*)(xh + (size_t)i * 4);
            p[0] = __floats2half2_rn(v.x, v.y);
            p[1] = __floats2half2_rn(v.z, v.w);
        }
    } else if (b < nbCvt + nbZero) {
        int i = (b - nbCvt) * 256 + threadIdx.x;
        if (i < M) deg[i] = 0;
        if (i < NB_MAX) status[i] = 0;
    } else {
        int i = (b - nbCvt - nbZero) * 256 + threadIdx.x;
        if (i < 16384) {
            int k = i >> 7, n = i & 127;
            wt[n * 128 + k] = __float2half_rn(__ldg(W1 + k * 128 + n));
        } else if (i < 32768) {
            int j = i - 16384, k = j >> 7, n = j & 127;
            wt[16384 + n * 128 + k] = __float2half_rn(__ldg(W2 + k * 128 + n));
        } else if (i < 40960) {
            int j = i - 32768, k = j >> 6, n = j & 63;
            wt[32768 + n * 128 + k] = __float2half_rn(__ldg(W3 + k * 64 + n));
        }
    }
}

// ======================= CSR build =========================================
__global__ void k_count(int* deg, const int* __restrict__ dst,
                        int* __restrict__ rank, int E) {
    int e = blockIdx.x * blockDim.x + threadIdx.x;
    if (e < E) rank[e] = atomicAdd(&deg[dst[e]], 1);
}

__global__ void __launch_bounds__(SCAN_BLK)
k_scanall(const int* __restrict__ deg, int* __restrict__ off,
          float* __restrict__ dinv, int* status, int n, int E) {
    __shared__ int sh[SCAN_BLK];
    __shared__ int s_excl;
    const int tid  = threadIdx.x;
    const int tile = blockIdx.x;
    const int i = tile * SCAN_BLK + tid;

    int x = (i < n) ? deg[i] : 0;
    if (i < n) dinv[i] = (x > 0) ? rsqrtf((float)x) : 0.0f;
    sh[tid] = x;
    __syncthreads();
#pragma unroll
    for (int s = 1; s < SCAN_BLK; s <<= 1) {
        int v = (tid >= s) ? sh[tid - s] : 0;
        __syncthreads();
        sh[tid] += v;
        __syncthreads();
    }
    int incl = sh[tid];

    if (tid == SCAN_BLK - 1)
        atomicExch(&status[tile], sh[SCAN_BLK - 1] | AGG_FLAG);

    if (tid < 32) {
        int sum = 0;
        for (int t = tid; t < tile; t += 32) {
            int s;
            do { s = atomicAdd(&status[t], 0); } while (!(s & AGG_FLAG));
            sum += s & 0x3FFFFFFF;
        }
#pragma unroll
        for (int o = 16; o; o >>= 1) sum += __shfl_xor_sync(0xFFFFFFFF, sum, o);
        if (tid == 0) s_excl = sum;
    }
    __syncthreads();

    if (i < n) off[i] = s_excl + incl - x;   // exclusive
    if (i == 0) off[n] = E;
}

__global__ void k_place(const int* __restrict__ src, const int* __restrict__ dst,
                        const int* __restrict__ off, const int* __restrict__ rank,
                        int* __restrict__ csr, int E) {
    int e = blockIdx.x * blockDim.x + threadIdx.x;
    if (e < E) {
        int slot = __ldg(off + dst[e]) + rank[e];
        csr[slot] = src[e];
    }
}

// ======================= HMMA GEMM (fp16 in/out, cp.async) =================
__device__ __forceinline__ void ldmx4(uint32_t* r, uint32_t addr) {
    asm volatile("ldmatrix.sync.aligned.m8n8.x4.shared.b16 {%0,%1,%2,%3}, [%4];"
                 : "=r"(r[0]), "=r"(r[1]), "=r"(r[2]), "=r"(r[3]) : "r"(addr));
}
__device__ __forceinline__ void ldmx2(uint32_t* r, uint32_t addr) {
    asm volatile("ldmatrix.sync.aligned.m8n8.x2.shared.b16 {%0,%1}, [%2];"
                 : "=r"(r[0]), "=r"(r[1]) : "r"(addr));
}
__device__ __forceinline__ void mma16816(float* c, const uint32_t* a, const uint32_t* b) {
    asm volatile("mma.sync.aligned.m16n8k16.row.col.f32.f16.f16.f32 "
                 "{%0,%1,%2,%3}, {%4,%5,%6,%7}, {%8,%9}, {%0,%1,%2,%3};"
                 : "+f"(c[0]), "+f"(c[1]), "+f"(c[2]), "+f"(c[3])
                 : "r"(a[0]), "r"(a[1]), "r"(a[2]), "r"(a[3]), "r"(b[0]), "r"(b[1]));
}
__device__ __forceinline__ void cpa16(uint32_t smem, const void* gmem) {
    asm volatile("cp.async.cg.shared.global [%0], [%1], 16;" :: "r"(smem), "l"(gmem));
}

template <int BN>
__global__ void __launch_bounds__(BN * 2)
k_gemm(const __half* __restrict__ A, const __half* __restrict__ Wt,
       __half* __restrict__ C, const float* __restrict__ dinv,
       int M, int relu_in) {
    constexpr int NT  = BN * 2;
    constexpr int NWN = BN / 32;

    extern __shared__ __half sm[];
    __half* As  = sm;                    // [128][APITCH]
    __half* Wts = sm + 128 * APITCH;     // [BN][APITCH]

    const int tid  = threadIdx.x;
    const int wid  = tid >> 5;
    const int lane = tid & 31;
    const int wm   = wid / NWN;
    const int wn   = wid % NWN;
    const int brow = blockIdx.x * 128;

    const uint32_t asb = (uint32_t)__cvta_generic_to_shared(As);
    const uint32_t wsb = (uint32_t)__cvta_generic_to_shared(Wts);

#pragma unroll
    for (int idx = tid; idx < 128 * 16; idx += NT) {
        int row = idx >> 4, ch = idx & 15;
        cpa16(asb + (uint32_t)(row * APITCH + ch * 8) * 2,
              A + ((size_t)(brow + row) * 128 + ch * 8));
    }
#pragma unroll
    for (int idx = tid; idx < BN * 16; idx += NT) {
        int n = idx >> 4, ch = idx & 15;
        cpa16(wsb + (uint32_t)(n * APITCH + ch * 8) * 2,
              Wt + ((size_t)n * 128 + ch * 8));
    }
    asm volatile("cp.async.commit_group;");
    asm volatile("cp.async.wait_group 0;" ::: "memory");
    __syncthreads();

    float acc[4][4][4];
#pragma unroll
    for (int i = 0; i < 4; i++)
#pragma unroll
        for (int j = 0; j < 4; j++)
#pragma unroll
            for (int q = 0; q < 4; q++) acc[i][j][q] = 0.0f;

    const int aRow0 = wm * 64 + (lane & 15);
    const int aKoff = (lane >> 4) * 8;
    const int bRow0 = wn * 32 + (lane & 7);
    const int bKoff = ((lane >> 3) & 1) * 8;
    const __half2 z2 = __floats2half2_rn(0.f, 0.f);

#pragma unroll
    for (int ks = 0; ks < 8; ks++) {
        uint32_t a[4][4], b[4][2];
#pragma unroll
        for (int mf = 0; mf < 4; mf++)
            ldmx4(a[mf], asb + (uint32_t)(((aRow0 + mf * 16) * APITCH) + ks * 16 + aKoff) * 2);
        if (relu_in) {
#pragma unroll
            for (int mf = 0; mf < 4; mf++)
#pragma unroll
                for (int q = 0; q < 4; q++) {
                    __half2 v = *(__half2*)&a[mf][q];
                    v = __hmax2(v, z2);
                    a[mf][q] = *(uint32_t*)&v;
                }
        }
#pragma unroll
        for (int nf = 0; nf < 4; nf++)
            ldmx2(b[nf], wsb + (uint32_t)(((bRow0 + nf * 8) * APITCH) + ks * 16 + bKoff) * 2);
#pragma unroll
        for (int mf = 0; mf < 4; mf++)
#pragma unroll
            for (int nf = 0; nf < 4; nf++)
                mma16816(acc[mf][nf], a[mf], b[nf]);
    }

    // ---- epilogue: dinv scale, fp16 store ----
    const int rbase = brow + wm * 64 + (lane >> 2);
    const int cbase = wn * 32 + (lane & 3) * 2;
#pragma unroll
    for (int mf = 0; mf < 4; mf++) {
        int r0 = rbase + mf * 16;
        int r1 = r0 + 8;
        float s0 = (r0 < M) ? __ldg(dinv + r0) : 0.0f;
        float s1 = (r1 < M) ? __ldg(dinv + r1) : 0.0f;
#pragma unroll
        for (int nf = 0; nf < 4; nf++) {
            int col = cbase + nf * 8;
            if (r0 < M)
                *(__half2*)(C + (size_t)r0 * BN + col) =
                    __floats2half2_rn(acc[mf][nf][0] * s0, acc[mf][nf][1] * s0);
            if (r1 < M)
                *(__half2*)(C + (size_t)r1 * BN + col) =
                    __floats2half2_rn(acc[mf][nf][2] * s1, acc[mf][nf][3] * s1);
        }
    }
}

// ===================== CSR gather-sum ======================================
// warp=node, 8B loads, depth-3 fp16 tree over each 8-edge group.
__global__ void __launch_bounds__(256)
k_agg128(const __half* __restrict__ h, const int* __restrict__ off,
         const int* __restrict__ csr, const float* __restrict__ dinv,
         const float* __restrict__ bias, __half* __restrict__ out, int Nn) {
    int gt = blockIdx.x * blockDim.x + threadIdx.x;
    int node = gt >> 5;
    int lane = gt & 31;
    if (node >= Nn) return;
    int i  = __ldg(off + node);
    int s1 = __ldg(off + node + 1);
    const uint2* hp = (const uint2*)h;   // row stride = 32 uint2

    float4 acc = make_float4(0.f, 0.f, 0.f, 0.f);
#pragma unroll 1
    for (; i + 8 <= s1; i += 8) {
        int s[8];
#pragma unroll
        for (int j = 0; j < 8; j++) s[j] = __ldg(csr + i + j);
        uint2 v[8];
#pragma unroll
        for (int j = 0; j < 8; j++) v[j] = __ldg(hp + (size_t)s[j] * 32 + lane);
        // depth-3 fp16 tree over all 8 edges, one convert per word
        __half2 tx = __hadd2(
            __hadd2(__hadd2(H2(v[0].x), H2(v[1].x)), __hadd2(H2(v[2].x), H2(v[3].x))),
            __hadd2(__hadd2(H2(v[4].x), H2(v[5].x)), __hadd2(H2(v[6].x), H2(v[7].x))));
        __half2 ty = __hadd2(
            __hadd2(__hadd2(H2(v[0].y), H2(v[1].y)), __hadd2(H2(v[2].y), H2(v[3].y))),
            __hadd2(__hadd2(H2(v[4].y), H2(v[5].y)), __hadd2(H2(v[6].y), H2(v[7].y))));
        float2 fx = __half22float2(tx);
        float2 fy = __half22float2(ty);
        acc.x += fx.x; acc.y += fx.y; acc.z += fy.x; acc.w += fy.y;
    }
    for (; i < s1; i++) {
        int s = __ldg(csr + i);
        uint2 v = __ldg(hp + (size_t)s * 32 + lane);
        float2 f0 = __half22float2(H2(v.x));
        float2 f1 = __half22float2(H2(v.y));
        acc.x += f0.x; acc.y += f0.y; acc.z += f1.x; acc.w += f1.y;
    }
    float dv = __ldg(dinv + node);
    float4 bv = __ldg((const float4*)bias + lane);
    __half2 o0 = __floats2half2_rn(acc.x * dv + bv.x, acc.y * dv + bv.y);
    __half2 o1 = __floats2half2_rn(acc.z * dv + bv.z, acc.w * dv + bv.w);
    uint2 ov;
    ov.x = *(uint32_t*)&o0; ov.y = *(uint32_t*)&o1;
    *((uint2*)out + (size_t)node * 32 + lane) = ov;
}

__global__ void __launch_bounds__(256)
k_agg64(const __half* __restrict__ h, const int* __restrict__ off,
        const int* __restrict__ csr, const float* __restrict__ dinv,
        const float* __restrict__ bias, float* __restrict__ out, int Nn) {
    int gt = blockIdx.x * blockDim.x + threadIdx.x;
    int node = gt >> 4;
    int lane = gt & 15;
    if (node >= Nn) return;
    int i  = __ldg(off + node);
    int s1 = __ldg(off + node + 1);
    const uint2* hp = (const uint2*)h;   // row stride = 16 uint2

    float4 acc = make_float4(0.f, 0.f, 0.f, 0.f);
#pragma unroll 1
    for (; i + 8 <= s1; i += 8) {
        int s[8];
#pragma unroll
        for (int j = 0; j < 8; j++) s[j] = __ldg(csr + i + j);
        uint2 v[8];
#pragma unroll
        for (int j = 0; j < 8; j++) v[j] = __ldg(hp + (size_t)s[j] * 16 + lane);
        __half2 tx = __hadd2(
            __hadd2(__hadd2(H2(v[0].x), H2(v[1].x)), __hadd2(H2(v[2].x), H2(v[3].x))),
            __hadd2(__hadd2(H2(v[4].x), H2(v[5].x)), __hadd2(H2(v[6].x), H2(v[7].x))));
        __half2 ty = __hadd2(
            __hadd2(__hadd2(H2(v[0].y), H2(v[1].y)), __hadd2(H2(v[2].y), H2(v[3].y))),
            __hadd2(__hadd2(H2(v[4].y), H2(v[5].y)), __hadd2(H2(v[6].y), H2(v[7].y))));
        float2 fx = __half22float2(tx);
        float2 fy = __half22float2(ty);
        acc.x += fx.x; acc.y += fx.y; acc.z += fy.x; acc.w += fy.y;
    }
    for (; i < s1; i++) {
        int s = __ldg(csr + i);
        uint2 v = __ldg(hp + (size_t)s * 16 + lane);
        float2 f0 = __half22float2(H2(v.x));
        float2 f1 = __half22float2(H2(v.y));
        acc.x += f0.x; acc.y += f0.y; acc.z += f1.x; acc.w += f1.y;
    }
    float dv = __ldg(dinv + node);
    float4 bv = __ldg((const float4*)bias + lane);
    float4 o = make_float4(acc.x * dv + bv.x, acc.y * dv + bv.y,
                           acc.z * dv + bv.z, acc.w * dv + bv.w);
    *(float4*)(out + (size_t)node * 64 + lane * 4) = o;
}

// ---------------------------------------------------------------------------
extern "C" void kernel_launch(void* const* d_in, const int* in_sizes, int n_in,
                              void* d_out, int out_size) {
    const float* x  = (const float*)d_in[0];
    const int*   ei = (const int*)  d_in[1];
    const float* W1 = (const float*)d_in[2];
    const float* b1 = (const float*)d_in[3];
    const float* W2 = (const float*)d_in[4];
    const float* b2 = (const float*)d_in[5];
    const float* W3 = (const float*)d_in[6];
    const float* b3 = (const float*)d_in[7];

    const int E = in_sizes[1] / 2;
    const int M = in_sizes[0] / 128;
    const int* src = ei;
    const int* dst = ei + E;

    __half *h, *a, *wt;
    float* dinv;
    int *deg, *off, *rank, *csr, *status;
    cudaGetSymbolAddress((void**)&h,      g_h);
    cudaGetSymbolAddress((void**)&a,      g_a);
    cudaGetSymbolAddress((void**)&wt,     g_wt);
    cudaGetSymbolAddress((void**)&deg,    g_deg);
    cudaGetSymbolAddress((void**)&dinv,   g_dinv);
    cudaGetSymbolAddress((void**)&off,    g_off);
    cudaGetSymbolAddress((void**)&rank,   g_rank);
    cudaGetSymbolAddress((void**)&csr,    g_csr);
    cudaGetSymbolAddress((void**)&status, g_status);
    float* out = (float*)d_out;

    const int nb = (M + SCAN_BLK - 1) / SCAN_BLK;
    const int smem128 = (128 + 128) * APITCH * 2;   // 69632
    const int smem64  = (128 + 64)  * APITCH * 2;   // 52224
    cudaFuncSetAttribute(k_gemm<128>, cudaFuncAttributeMaxDynamicSharedMemorySize, smem128);
    cudaFuncSetAttribute(k_gemm<64>,  cudaFuncAttributeMaxDynamicSharedMemorySize, smem64);

    // --- fused prep: deg=0, status=0, xh=fp16(x), Wt=fp16(W^T) ---
    const int n4     = M * 32;
    const int nbCvt  = (n4 + 255) / 256;
    const int nbZero = (M + 255) / 256;
    const int nbWt   = (40960 + 255) / 256;
    k_prep<<<nbCvt + nbZero + nbWt, 256>>>(x, a, deg, status, W1, W2, W3, wt,
                                           n4, M, nbCvt, nbZero);

    // --- CSR build (rank captured in count; place is atomic-free) ---
    k_count  <<<(E + 255) / 256, 256>>>(deg, dst, rank, E);
    k_scanall<<<nb, SCAN_BLK>>>(deg, off, dinv, status, M, E);
    k_place  <<<(E + 255) / 256, 256>>>(src, dst, off, rank, csr, E);

    const int gtiles = (M + 127) / 128;

    // --- layer 1 ---
    k_gemm<128><<<gtiles, 256, smem128>>>(a, wt, h, dinv, M, 0);
    k_agg128<<<(M * 32 + 255) / 256, 256>>>(h, off, csr, dinv, b1, a, M);

    // --- layer 2 ---
    k_gemm<128><<<gtiles, 256, smem128>>>(a, wt + 16384, h, dinv, M, 1);
    k_agg128<<<(M * 32 + 255) / 256, 256>>>(h, off, csr, dinv, b2, a, M);

    // --- layer 3 (N=64) ---
    k_gemm<64><<<gtiles, 128, smem64>>>(a, wt + 32768, h, dinv, M, 1);
    k_agg64<<<(M * 16 + 255) / 256, 256>>>(h, off, csr, dinv, b3, out, M);
}